// round 11
// baseline (speedup 1.0000x reference)
#include <cuda_runtime.h>
#include <math_constants.h>
#include <cstdint>

#define BATCH 8
#define CC 256
#define NPIX 1024
#define NHEAD 8
#define HDIM 32
#define DDIM 32

// Scratch (device globals)
__device__ float g_qkv[BATCH * 3 * CC * NPIX];
__device__ float g_ctx[BATCH * CC * NPIX];
__device__ float g_ao[BATCH * CC * NPIX];
__device__ float g_feats[4 * BATCH * CC * NPIX];
__device__ float2 g_wT2[2752512];                 // conv weights [tap][cpair][o] f2
__device__ float g_part[2 * BATCH * CC * NPIX];   // k7 split-K partials
__device__ float g_bnA[4 * CC];
__device__ float g_bnB[4 * CC];
__device__ float g_S[BATCH * CC];
__device__ float g_attnw[4 * BATCH * CC];
__device__ float g_qkvwT[768 * 256];
__device__ float g_outwT[256 * 256];

// f2-unit branch offsets: k1@0(1 tap), k3@32768(9), k5@327680(25), k7@1146880(49)
#define WT2_OFF1 0
#define WT2_OFF3 32768
#define WT2_OFF5 327680
#define WT2_OFF7 1146880

__device__ __forceinline__ float to_tf32(float x) {
    uint32_t y;
    asm("cvt.rna.tf32.f32 %0, %1;" : "=r"(y) : "f"(x));
    return __uint_as_float(y);
}
__device__ __forceinline__ uint32_t to_tf32_u(float x) {
    uint32_t y;
    asm("cvt.rna.tf32.f32 %0, %1;" : "=r"(y) : "f"(x));
    return y;
}

__device__ __forceinline__ void mma_tf32(float* d, const uint32_t* a, const uint32_t* b) {
    asm volatile(
        "mma.sync.aligned.m16n8k8.row.col.f32.tf32.tf32.f32 "
        "{%0,%1,%2,%3}, {%4,%5,%6,%7}, {%8,%9}, {%0,%1,%2,%3};"
        : "+f"(d[0]), "+f"(d[1]), "+f"(d[2]), "+f"(d[3])
        : "r"(a[0]), "r"(a[1]), "r"(a[2]), "r"(a[3]), "r"(b[0]), "r"(b[1]));
}

// ---------------------------------------------------------------------------
// Repack conv weights OIHW -> [tap][cpair][o] float2 (channels c, c+4), tf32
// cpair cp: chunk = cp>>3, pi = cp&7, s = pi>>2, lk = pi&3
//   c_x = chunk*16 + s*8 + lk ; c_y = c_x + 4
// ---------------------------------------------------------------------------
__global__ void wtrans_kernel(const float* __restrict__ w1, const float* __restrict__ w3,
                              const float* __restrict__ w5, const float* __restrict__ w7) {
    int idx = blockIdx.x * 256 + threadIdx.x;
    if (idx >= 2752512) return;
    const float* src;
    int k2, base;
    if (idx < 327680)       { if (idx < 32768) { src = w1; k2 = 1;  base = 0; }
                              else              { src = w3; k2 = 9;  base = 32768; } }
    else if (idx < 1146880) { src = w5; k2 = 25; base = 327680; }
    else                    { src = w7; k2 = 49; base = 1146880; }
    int r   = idx - base;
    int o   = r & 255;
    int cp  = (r >> 8) & 127;
    int tap = r >> 15;
    int chunk = cp >> 3, pi = cp & 7;
    int cx = chunk * 16 + (pi >> 2) * 8 + (pi & 3);
    float vx = src[(o * 256 + cx) * k2 + tap];
    float vy = src[(o * 256 + cx + 4) * k2 + tap];
    g_wT2[idx] = make_float2(to_tf32(vx), to_tf32(vy));
}

// ---------------------------------------------------------------------------
// Transpose projection weights: W[m][k] -> WT[k][m], tf32
// ---------------------------------------------------------------------------
__global__ void wsplit_kernel(const float* __restrict__ qkv_w,
                              const float* __restrict__ out_w) {
    int idx = blockIdx.x * 256 + threadIdx.x;
    if (idx < 196608) {
        int m = idx / 256, k = idx & 255;
        g_qkvwT[k * 768 + m] = to_tf32(qkv_w[idx]);
    } else {
        int r = idx - 196608;
        int m = r / 256, k = r & 255;
        g_outwT[k * 256 + m] = to_tf32(out_w[r]);
    }
}

// ---------------------------------------------------------------------------
// GEMM via tf32 mma (single tf32). 3 CTAs/SM for latency hiding.
// ---------------------------------------------------------------------------
#define GW_STRIDE 72
#define GX_STRIDE 264

__global__ __launch_bounds__(256, 3) void gemm_mma_kernel(
    const float* __restrict__ WT, const float* __restrict__ X,
    float* __restrict__ D, int M) {
    __shared__ float sW[16 * GW_STRIDE];
    __shared__ float sX[16 * GX_STRIDE];
    int tid = threadIdx.x;
    int n0 = blockIdx.x * 256, m0 = blockIdx.y * 64, b = blockIdx.z;
    const float* Xb = X + (size_t)b * 256 * NPIX;
    float*       Db = D + (size_t)b * M * NPIX;
    int wid = tid >> 5, lane = tid & 31;
    int g = lane >> 2, tq = lane & 3;
    int mw = (wid >> 2) * 32;
    int nw = (wid & 3) * 64;
    float acc[2][8][4] = {};
    for (int k0 = 0; k0 < 256; k0 += 16) {
        __syncthreads();
        {
            int k = tid >> 4, col = (tid & 15) * 4;
            *(float4*)&sW[k * GW_STRIDE + col] =
                *(const float4*)&WT[(size_t)(k0 + k) * M + m0 + col];
        }
        for (int i = tid; i < 1024; i += 256) {
            int k = i >> 6, c4 = (i & 63) * 4;
            float4 v = *(const float4*)&Xb[(size_t)(k0 + k) * NPIX + n0 + c4];
            v.x = to_tf32(v.x); v.y = to_tf32(v.y);
            v.z = to_tf32(v.z); v.w = to_tf32(v.w);
            *(float4*)&sX[k * GX_STRIDE + c4] = v;
        }
        __syncthreads();
#pragma unroll
        for (int s = 0; s < 2; s++) {
            int k = 8 * s + tq;
            uint32_t a[2][4];
#pragma unroll
            for (int t = 0; t < 2; t++) {
                int m = mw + 16 * t + g;
                a[t][0] = __float_as_uint(sW[k * GW_STRIDE + m]);
                a[t][1] = __float_as_uint(sW[k * GW_STRIDE + m + 8]);
                a[t][2] = __float_as_uint(sW[(k + 4) * GW_STRIDE + m]);
                a[t][3] = __float_as_uint(sW[(k + 4) * GW_STRIDE + m + 8]);
            }
#pragma unroll
            for (int j = 0; j < 8; j++) {
                int nj = nw + 8 * j + g;
                uint32_t bb[2];
                bb[0] = __float_as_uint(sX[k * GX_STRIDE + nj]);
                bb[1] = __float_as_uint(sX[(k + 4) * GX_STRIDE + nj]);
#pragma unroll
                for (int t = 0; t < 2; t++) mma_tf32(acc[t][j], a[t], bb);
            }
        }
    }
#pragma unroll
    for (int t = 0; t < 2; t++) {
        int o = m0 + mw + 16 * t + g;
#pragma unroll
        for (int j = 0; j < 8; j++) {
            int n = n0 + nw + 8 * j + 2 * tq;
            *(float2*)&Db[(size_t)o * NPIX + n] =
                make_float2(acc[t][j][0], acc[t][j][1]);
            *(float2*)&Db[(size_t)(o + 8) * NPIX + n] =
                make_float2(acc[t][j][2], acc[t][j][3]);
        }
    }
}

// ---------------------------------------------------------------------------
// Attention via tf32 mma (unchanged - passing)
// ---------------------------------------------------------------------------
#define ATTN_SMEM_BYTES 55296

__global__ __launch_bounds__(256) void attn_mma_kernel(const float* __restrict__ qkv,
                                                       float* __restrict__ ctx) {
    extern __shared__ float sm[];
    float* sK = sm;
    float* sV = sm + 2304;
    float* sQ = sm + 4608;

    int t    = threadIdx.x;
    int wid  = t >> 5, lane = t & 31;
    int g    = lane >> 2;
    int tq   = lane & 3;
    int qw   = wid * 16;
    float* sP = sm + 4608 + wid * (16 * 72);

    int bh = blockIdx.y;
    int b = bh >> 3, h = bh & 7;
    int q0 = blockIdx.x * 128;
    const float* base = qkv + (size_t)b * (3 * CC * NPIX);
    const float* qp = base + (h * HDIM) * NPIX;
    const float* kp = base + (CC + h * HDIM) * NPIX;
    const float* vp = base + (2 * CC + h * HDIM) * NPIX;
    const float scale = 0.17677669529663687f;

    for (int i = t; i < 1024; i += 256) {
        int d  = i >> 5;
        int q4 = (i & 31) * 4;
        float4 v = *(const float4*)&qp[(size_t)d * NPIX + q0 + q4];
        sQ[(q4 + 0) * 36 + d] = v.x * scale;
        sQ[(q4 + 1) * 36 + d] = v.y * scale;
        sQ[(q4 + 2) * 36 + d] = v.z * scale;
        sQ[(q4 + 3) * 36 + d] = v.w * scale;
    }
    __syncthreads();

    uint32_t qf[4][4];
#pragma unroll
    for (int kc = 0; kc < 4; kc++) {
#pragma unroll
        for (int r = 0; r < 4; r++) {
            int row = qw + ((r & 1) ? g + 8 : g);
            int col = 8 * kc + tq + ((r >> 1) ? 4 : 0);
            qf[kc][r] = to_tf32_u(sQ[row * 36 + col]);
        }
    }

    float mrow[2] = {-1e30f, -1e30f};
    float lrow[2] = {0.f, 0.f};
    float oacc[4][4] = {};

    for (int k0 = 0; k0 < NPIX; k0 += 64) {
        __syncthreads();
        for (int i = t; i < 512; i += 256) {
            int d  = i >> 4;
            int c4 = (i & 15) * 4;
            float4 v = *(const float4*)&kp[(size_t)d * NPIX + k0 + c4];
            v.x = to_tf32(v.x); v.y = to_tf32(v.y);
            v.z = to_tf32(v.z); v.w = to_tf32(v.w);
            *(float4*)&sK[d * 72 + c4] = v;
            float4 vv = *(const float4*)&vp[(size_t)d * NPIX + k0 + c4];
            vv.x = to_tf32(vv.x); vv.y = to_tf32(vv.y);
            vv.z = to_tf32(vv.z); vv.w = to_tf32(vv.w);
            *(float4*)&sV[d * 72 + c4] = vv;
        }
        __syncthreads();

        float sv[8][4];
#pragma unroll
        for (int nt = 0; nt < 8; nt++) {
            float acc[4] = {0.f, 0.f, 0.f, 0.f};
#pragma unroll
            for (int kc = 0; kc < 4; kc++) {
                int i0 = (8 * kc + tq) * 72 + 8 * nt + g;
                int i1 = (8 * kc + tq + 4) * 72 + 8 * nt + g;
                uint32_t bb[2] = {__float_as_uint(sK[i0]), __float_as_uint(sK[i1])};
                mma_tf32(acc, qf[kc], bb);
            }
            sv[nt][0] = acc[0]; sv[nt][1] = acc[1];
            sv[nt][2] = acc[2]; sv[nt][3] = acc[3];
        }

        float tm0 = -1e30f, tm1 = -1e30f;
#pragma unroll
        for (int nt = 0; nt < 8; nt++) {
            tm0 = fmaxf(tm0, fmaxf(sv[nt][0], sv[nt][1]));
            tm1 = fmaxf(tm1, fmaxf(sv[nt][2], sv[nt][3]));
        }
        tm0 = fmaxf(tm0, __shfl_xor_sync(0xffffffffu, tm0, 1));
        tm0 = fmaxf(tm0, __shfl_xor_sync(0xffffffffu, tm0, 2));
        tm1 = fmaxf(tm1, __shfl_xor_sync(0xffffffffu, tm1, 1));
        tm1 = fmaxf(tm1, __shfl_xor_sync(0xffffffffu, tm1, 2));
        float m0n = fmaxf(mrow[0], tm0);
        float m1n = fmaxf(mrow[1], tm1);
        float c0 = __expf(mrow[0] - m0n);
        float c1 = __expf(mrow[1] - m1n);
        mrow[0] = m0n; mrow[1] = m1n;
        lrow[0] *= c0; lrow[1] *= c1;
#pragma unroll
        for (int dt = 0; dt < 4; dt++) {
            oacc[dt][0] *= c0; oacc[dt][1] *= c0;
            oacc[dt][2] *= c1; oacc[dt][3] *= c1;
        }
#pragma unroll
        for (int nt = 0; nt < 8; nt++) {
            float p0 = __expf(sv[nt][0] - m0n);
            float p1 = __expf(sv[nt][1] - m0n);
            float p2 = __expf(sv[nt][2] - m1n);
            float p3 = __expf(sv[nt][3] - m1n);
            lrow[0] += p0 + p1;
            lrow[1] += p2 + p3;
            *(float2*)&sP[g * 72 + 8 * nt + 2 * tq] =
                make_float2(to_tf32(p0), to_tf32(p1));
            *(float2*)&sP[(g + 8) * 72 + 8 * nt + 2 * tq] =
                make_float2(to_tf32(p2), to_tf32(p3));
        }
        __syncwarp();

#pragma unroll
        for (int kc = 0; kc < 8; kc++) {
            uint32_t a[4];
            a[0] = __float_as_uint(sP[g * 72 + 8 * kc + tq]);
            a[1] = __float_as_uint(sP[(g + 8) * 72 + 8 * kc + tq]);
            a[2] = __float_as_uint(sP[g * 72 + 8 * kc + tq + 4]);
            a[3] = __float_as_uint(sP[(g + 8) * 72 + 8 * kc + tq + 4]);
#pragma unroll
            for (int dt = 0; dt < 4; dt++) {
                uint32_t bb[2];
                bb[0] = __float_as_uint(sV[(8 * dt + g) * 72 + 8 * kc + tq]);
                bb[1] = __float_as_uint(sV[(8 * dt + g) * 72 + 8 * kc + tq + 4]);
                mma_tf32(oacc[dt], a, bb);
            }
        }
        __syncwarp();
    }

    lrow[0] += __shfl_xor_sync(0xffffffffu, lrow[0], 1);
    lrow[0] += __shfl_xor_sync(0xffffffffu, lrow[0], 2);
    lrow[1] += __shfl_xor_sync(0xffffffffu, lrow[1], 1);
    lrow[1] += __shfl_xor_sync(0xffffffffu, lrow[1], 2);
    float inv0 = 1.f / lrow[0];
    float inv1 = 1.f / lrow[1];
    float* cp = ctx + (size_t)b * (CC * NPIX) + (size_t)(h * HDIM) * NPIX;
    int qr0 = q0 + qw + g;
    int qr1 = qr0 + 8;
#pragma unroll
    for (int dt = 0; dt < 4; dt++) {
        int d0 = 8 * dt + 2 * tq;
        cp[(size_t)d0 * NPIX + qr0]       = oacc[dt][0] * inv0;
        cp[(size_t)(d0 + 1) * NPIX + qr0] = oacc[dt][1] * inv0;
        cp[(size_t)d0 * NPIX + qr1]       = oacc[dt][2] * inv1;
        cp[(size_t)(d0 + 1) * NPIX + qr1] = oacc[dt][3] * inv1;
    }
}

// ---------------------------------------------------------------------------
// Conv v4: pair-plane float2 layout -> all fragment loads are LDS.64.
//   Patch: 8 planes (pi = s*4+lk) of [14 rows x 40 cols] float2 (ch k, k+4),
//          plane stride 564 f2. A: [pi][64 o] float2, stride 68 f2.
// k1/k3/k5: fused BN+ReLU epilogue -> feats. k7: 2 splits -> g_part, epi.
// ---------------------------------------------------------------------------
#define PL2 564                       // patch plane stride (f2)
#define A2S 68                        // A plane stride (f2)
#define A2_TAP (8 * A2S)              // 544 f2 per tap
#define A2_GRP (4 * A2_TAP)           // 4-tap group
#define CONV_SMEM_F2 (8 * PL2 + 2 * A2_GRP)    // 4512 + 4352 = 8864
#define CONV_SMEM_BYTES (CONV_SMEM_F2 * 8)     // 70912

__global__ __launch_bounds__(256, 2) void conv_mma_kernel(const float* __restrict__ in,
                                                          float* __restrict__ feats) {
    extern __shared__ float2 cs2[];
    float2* sPatch = cs2;
    float2* sA     = cs2 + 8 * PL2;

    int z = blockIdx.z;
    int ks, tap0, tap1, slot, kb, b;
    size_t wtoff2;
    bool fused;
    if (z < 16) {            // k7: 2 splits
        int s = z >> 3; b = z & 7;
        ks = 7; tap0 = s ? 24 : 0; tap1 = s ? 49 : 24;
        slot = s; kb = 3; fused = false; wtoff2 = WT2_OFF7;
    } else if (z < 24) {     // k5 fused
        b = z - 16; ks = 5; tap0 = 0; tap1 = 25;
        slot = 0; kb = 2; fused = true; wtoff2 = WT2_OFF5;
    } else if (z < 32) {     // k3 fused
        b = z - 24; ks = 3; tap0 = 0; tap1 = 9;
        slot = 0; kb = 1; fused = true; wtoff2 = WT2_OFF3;
    } else {                 // k1 fused
        b = z - 32; ks = 1; tap0 = 0; tap1 = 1;
        slot = 0; kb = 0; fused = true; wtoff2 = WT2_OFF1;
    }
    const int P = ks >> 1;
    const int rows = 8 + 2 * P;

    int n0 = blockIdx.x * 256;
    int m0 = blockIdx.y * 64;
    int r0 = n0 >> 5;
    int tid = threadIdx.x;
    int wid = tid >> 5, lane = tid & 31;
    int mw = (wid >> 2) * 32;
    int nw = (wid & 3) * 64;
    int lg = lane >> 2;
    int lk = lane & 3;

    // zero patch (halo + out-of-image rows stay zero)
    for (int i = tid; i < (8 * PL2) / 2; i += 256)
        *(float4*)&sPatch[i * 2] = make_float4(0.f, 0.f, 0.f, 0.f);

    int njoff[8];
#pragma unroll
    for (int j = 0; j < 8; j++) {
        int n = nw + 8 * j + lg;
        njoff[j] = (n >> 5) * 40 + (n & 31) + 4;
    }

    const float* inb = in + (size_t)b * (CC * NPIX);
    float acc[2][8][4] = {};

    for (int c0 = 0; c0 < 256; c0 += 16) {
        __syncthreads();
        // --- patch: channel c -> plane ((c>>3)<<2)+(c&3), comp (c>>2)&1 ---
        {
            int per_plane = rows * 8;
            int total = 16 * per_plane;
            for (int i = tid; i < total; i += 256) {
                int c  = i / per_plane;
                int rm = i - c * per_plane;
                int py = rm >> 3;
                int xq = (rm & 7) * 4;
                int iy = r0 - P + py;
                if ((unsigned)iy < 32u) {
                    float4 v = *(const float4*)&inb[(size_t)(c0 + c) * NPIX + iy * 32 + xq];
                    int p = ((c >> 3) << 2) + (c & 3);
                    int comp = (c >> 2) & 1;
                    float* dst = ((float*)&sPatch[p * PL2 + py * 40 + 4 + xq]) + comp;
                    dst[0] = to_tf32(v.x);
                    dst[2] = to_tf32(v.y);
                    dst[4] = to_tf32(v.z);
                    dst[6] = to_tf32(v.w);
                }
            }
        }
        // --- preload first tap group ---
        {
            size_t cb = wtoff2 + (size_t)(c0 >> 1) * 256;
            int gcnt = tap1 - tap0; if (gcnt > 4) gcnt = 4;
            for (int i = tid; i < gcnt * 256; i += 256) {
                int tg = i >> 8;
                int pi = (i >> 5) & 7;
                int c4 = (i & 31) * 2;
                *(float4*)&sA[tg * A2_TAP + pi * A2S + c4] =
                    *(const float4*)&g_wT2[cb + (size_t)(tap0 + tg) * 32768 +
                                           pi * 256 + m0 + c4];
            }
        }
        __syncthreads();

        int buf = 0;
        for (int g0 = tap0; g0 < tap1; g0 += 4) {
            int gcnt = tap1 - g0; if (gcnt > 4) gcnt = 4;
            int h0 = g0 + 4;
            if (h0 < tap1) {
                int hcnt = tap1 - h0; if (hcnt > 4) hcnt = 4;
                float2* dst = sA + (buf ^ 1) * A2_GRP;
                size_t cb = wtoff2 + (size_t)(c0 >> 1) * 256;
                for (int i = tid; i < hcnt * 256; i += 256) {
                    int tg = i >> 8;
                    int pi = (i >> 5) & 7;
                    int c4 = (i & 31) * 2;
                    *(float4*)&dst[tg * A2_TAP + pi * A2S + c4] =
                        *(const float4*)&g_wT2[cb + (size_t)(h0 + tg) * 32768 +
                                               pi * 256 + m0 + c4];
                }
            }
            for (int ti = 0; ti < gcnt; ti++) {
                int tap = g0 + ti;
                int ty = tap / ks;
                int tx = tap - ty * ks;
                int tadd = ty * 40 + tx - P;
                const float2* At = sA + buf * A2_GRP + ti * A2_TAP;
#pragma unroll
                for (int s = 0; s < 2; s++) {
                    int pi = s * 4 + lk;
                    uint32_t a[2][4];
#pragma unroll
                    for (int t = 0; t < 2; t++) {
                        float2 l = At[pi * A2S + mw + 16 * t + lg];
                        float2 h = At[pi * A2S + mw + 16 * t + lg + 8];
                        a[t][0] = __float_as_uint(l.x);
                        a[t][1] = __float_as_uint(h.x);
                        a[t][2] = __float_as_uint(l.y);
                        a[t][3] = __float_as_uint(h.y);
                    }
                    uint32_t bb[8][2];
#pragma unroll
                    for (int j = 0; j < 8; j++) {
                        float2 bv = sPatch[pi * PL2 + njoff[j] + tadd];
                        bb[j][0] = __float_as_uint(bv.x);
                        bb[j][1] = __float_as_uint(bv.y);
                    }
#pragma unroll
                    for (int t = 0; t < 2; t++)
#pragma unroll
                        for (int j = 0; j < 8; j++) mma_tf32(acc[t][j], a[t], bb[j]);
                }
            }
            __syncthreads();
            buf ^= 1;
        }
    }

    if (fused) {
        float* fp = feats + (size_t)kb * (BATCH * CC * NPIX) + (size_t)b * (CC * NPIX);
#pragma unroll
        for (int t = 0; t < 2; t++) {
            int o = m0 + mw + 16 * t + lg;
            float A0 = g_bnA[kb * 256 + o],     B0 = g_bnB[kb * 256 + o];
            float A1 = g_bnA[kb * 256 + o + 8], B1 = g_bnB[kb * 256 + o + 8];
#pragma unroll
            for (int j = 0; j < 8; j++) {
                int n = n0 + nw + 8 * j + 2 * lk;
                *(float2*)&fp[(size_t)o * NPIX + n] = make_float2(
                    fmaxf(acc[t][j][0] * A0 + B0, 0.f),
                    fmaxf(acc[t][j][1] * A0 + B0, 0.f));
                *(float2*)&fp[(size_t)(o + 8) * NPIX + n] = make_float2(
                    fmaxf(acc[t][j][2] * A1 + B1, 0.f),
                    fmaxf(acc[t][j][3] * A1 + B1, 0.f));
            }
        }
    } else {
        float* pp = g_part + (size_t)slot * (BATCH * CC * NPIX) + (size_t)b * (CC * NPIX);
#pragma unroll
        for (int t = 0; t < 2; t++) {
            int o = m0 + mw + 16 * t + lg;
#pragma unroll
            for (int j = 0; j < 8; j++) {
                int n = n0 + nw + 8 * j + 2 * lk;
                *(float2*)&pp[(size_t)o * NPIX + n] =
                    make_float2(acc[t][j][0], acc[t][j][1]);
                *(float2*)&pp[(size_t)(o + 8) * NPIX + n] =
                    make_float2(acc[t][j][2], acc[t][j][3]);
            }
        }
    }
}

// ---------------------------------------------------------------------------
// BN constants
// ---------------------------------------------------------------------------
__global__ void bnprep_kernel(const float* __restrict__ conv_b,
                              const float* __restrict__ gamma,
                              const float* __restrict__ beta,
                              const float* __restrict__ mean,
                              const float* __restrict__ var) {
    int i = threadIdx.x;
    float inv = gamma[i] * rsqrtf(var[i] + 1e-5f);
    g_bnA[i] = inv;
    g_bnB[i] = beta[i] - mean[i] * inv + conv_b[i] * inv;
}

// ---------------------------------------------------------------------------
// Epilogue (k7 only): sum the 2 split slots, BN + ReLU -> feats[3]
// ---------------------------------------------------------------------------
__global__ __launch_bounds__(256) void epi_kernel(float* __restrict__ feats) {
    int row = blockIdx.x;          // b*256 + o, 2048 rows
    int o   = row & 255;
    float Aa = g_bnA[768 + o];
    float Bb = g_bnB[768 + o];
    size_t base = (size_t)row * NPIX + threadIdx.x * 4;
    const size_t SL = (size_t)BATCH * CC * NPIX;
    float4 s0 = *(const float4*)&g_part[base];
    float4 s1 = *(const float4*)&g_part[SL + base];
    float4 v;
    v.x = fmaxf((s0.x + s1.x) * Aa + Bb, 0.f);
    v.y = fmaxf((s0.y + s1.y) * Aa + Bb, 0.f);
    v.z = fmaxf((s0.z + s1.z) * Aa + Bb, 0.f);
    v.w = fmaxf((s0.w + s1.w) * Aa + Bb, 0.f);
    *(float4*)&feats[3 * SL + base] = v;
}

// ---------------------------------------------------------------------------
// S[b,c] = mean over pixels of sum-over-branches of feats
// ---------------------------------------------------------------------------
__global__ __launch_bounds__(128) void sreduce_kernel(float* __restrict__ S) {
    int bc = blockIdx.x;
    int t  = threadIdx.x;
    float s = 0.f;
#pragma unroll
    for (int k = 0; k < 4; k++) {
        const float* p = g_feats + ((size_t)k * (BATCH * CC) + bc) * NPIX;
        for (int n = t; n < NPIX; n += 128) s += p[n];
    }
#pragma unroll
    for (int off = 16; off; off >>= 1) s += __shfl_down_sync(0xffffffffu, s, off);
    __shared__ float red[4];
    if ((t & 31) == 0) red[t >> 5] = s;
    __syncthreads();
    if (t == 0) S[bc] = (red[0] + red[1] + red[2] + red[3]) * (1.f / 1024.f);
}

// ---------------------------------------------------------------------------
// fc -> per-branch logits -> softmax over branches
// ---------------------------------------------------------------------------
__global__ __launch_bounds__(256) void select_kernel(
    const float* __restrict__ S, const float* __restrict__ fc_w,
    const float* __restrict__ fc_b, const float* __restrict__ fcs_w,
    const float* __restrict__ fcs_b, float* __restrict__ attnw) {
    __shared__ float Ss[BATCH * CC];
    __shared__ float Zs[BATCH * DDIM];
    int t = threadIdx.x;
    for (int i = t; i < BATCH * CC; i += 256) Ss[i] = S[i];
    __syncthreads();
    {
        int b = t >> 5, d = t & 31;
        float z = fc_b[d];
        const float* wr = fc_w + d * CC;
        for (int c = 0; c < CC; c++) z += Ss[b * CC + c] * wr[c];
        Zs[b * DDIM + d] = z;
    }
    __syncthreads();
    for (int it = 0; it < 8; it++) {
        int idx = it * 256 + t;
        int b = idx >> 8, c = idx & 255;
        float lg[4];
#pragma unroll
        for (int k = 0; k < 4; k++) {
            float v = fcs_b[k * CC + c];
            const float* wp = fcs_w + ((size_t)k * CC + c) * DDIM;
#pragma unroll
            for (int d = 0; d < DDIM; d++) v += wp[d] * Zs[b * DDIM + d];
            lg[k] = v;
        }
        float mx  = fmaxf(fmaxf(lg[0], lg[1]), fmaxf(lg[2], lg[3]));
        float e0 = __expf(lg[0] - mx), e1 = __expf(lg[1] - mx);
        float e2 = __expf(lg[2] - mx), e3 = __expf(lg[3] - mx);
        float inv = 1.f / (e0 + e1 + e2 + e3);
        attnw[0 * 2048 + idx] = e0 * inv;
        attnw[1 * 2048 + idx] = e1 * inv;
        attnw[2 * 2048 + idx] = e2 * inv;
        attnw[3 * 2048 + idx] = e3 * inv;
    }
}

// ---------------------------------------------------------------------------
// V = sum_k attn[k,b,c] * feats[k,b,c,:]
// ---------------------------------------------------------------------------
__global__ __launch_bounds__(256) void combine_kernel(const float* __restrict__ attnw,
                                                      float* __restrict__ out) {
    int idx = blockIdx.x * 256 + threadIdx.x;
    if (idx >= BATCH * CC * NPIX) return;
    int bc = idx >> 10;
    const size_t KSTRIDE = (size_t)BATCH * CC * NPIX;
    float v = attnw[bc]        * g_feats[idx] +
              attnw[2048 + bc] * g_feats[KSTRIDE + idx] +
              attnw[4096 + bc] * g_feats[2 * KSTRIDE + idx] +
              attnw[6144 + bc] * g_feats[3 * KSTRIDE + idx];
    out[idx] = v;
}

// ---------------------------------------------------------------------------
// Launch
// ---------------------------------------------------------------------------
extern "C" void kernel_launch(void* const* d_in, const int* in_sizes, int n_in,
                              void* d_out, int out_size) {
    const float* x      = (const float*)d_in[0];
    const float* qkv_w  = (const float*)d_in[1];
    const float* out_w  = (const float*)d_in[2];
    const float* w1     = (const float*)d_in[3];
    const float* w3     = (const float*)d_in[4];
    const float* w5     = (const float*)d_in[5];
    const float* w7     = (const float*)d_in[6];
    const float* conv_b = (const float*)d_in[7];
    const float* gamma  = (const float*)d_in[8];
    const float* beta   = (const float*)d_in[9];
    const float* mean   = (const float*)d_in[10];
    const float* var    = (const float*)d_in[11];
    const float* fc_w   = (const float*)d_in[12];
    const float* fc_b   = (const float*)d_in[13];
    const float* fcs_w  = (const float*)d_in[14];
    const float* fcs_b  = (const float*)d_in[15];
    float* out = (float*)d_out;

    float *p_qkv, *p_ctx, *p_ao, *p_feats, *p_S, *p_attnw;
    float *p_qw, *p_ow;
    cudaGetSymbolAddress((void**)&p_qkv,   g_qkv);
    cudaGetSymbolAddress((void**)&p_ctx,   g_ctx);
    cudaGetSymbolAddress((void**)&p_ao,    g_ao);
    cudaGetSymbolAddress((void**)&p_feats, g_feats);
    cudaGetSymbolAddress((void**)&p_S,     g_S);
    cudaGetSymbolAddress((void**)&p_attnw, g_attnw);
    cudaGetSymbolAddress((void**)&p_qw,    g_qkvwT);
    cudaGetSymbolAddress((void**)&p_ow,    g_outwT);

    static int attr_set = 0;
    if (!attr_set) {
        cudaFuncSetAttribute(attn_mma_kernel,
                             cudaFuncAttributeMaxDynamicSharedMemorySize,
                             ATTN_SMEM_BYTES);
        cudaFuncSetAttribute(conv_mma_kernel,
                             cudaFuncAttributeMaxDynamicSharedMemorySize,
                             CONV_SMEM_BYTES);
        attr_set = 1;
    }

    wtrans_kernel<<<10752, 256>>>(w1, w3, w5, w7);
    wsplit_kernel<<<1024, 256>>>(qkv_w, out_w);
    bnprep_kernel<<<1, 1024>>>(conv_b, gamma, beta, mean, var);

    gemm_mma_kernel<<<dim3(4, 12, 8), 256>>>(p_qw, x, p_qkv, 768);
    attn_mma_kernel<<<dim3(8, 64), 256, ATTN_SMEM_BYTES>>>(p_qkv, p_ctx);
    gemm_mma_kernel<<<dim3(4, 4, 8), 256>>>(p_ow, p_ctx, p_ao, 256);

    conv_mma_kernel<<<dim3(4, 4, 40), 256, CONV_SMEM_BYTES>>>(p_ao, p_feats);
    epi_kernel<<<2048, 256>>>(p_feats);

    sreduce_kernel<<<2048, 128>>>(p_S);
    select_kernel<<<1, 256>>>(p_S, fc_w, fc_b, fcs_w, fcs_b, p_attnw);
    combine_kernel<<<8192, 256>>>(p_attnw, out);
}

// round 14
// speedup vs baseline: 1.3606x; 1.3606x over previous
#include <cuda_runtime.h>
#include <cuda_fp16.h>
#include <cstdint>

#define BATCH 8
#define CC 256
#define NPIX 1024
#define HDIM 32
#define DDIM 32

__device__ float g_qkv[BATCH * 3 * CC * NPIX];
__device__ float g_ctx[BATCH * CC * NPIX];
__device__ float g_ao[BATCH * CC * NPIX];
__device__ float g_feats[4 * BATCH * CC * NPIX];
__device__ half2 g_wH2[2752512];                  // conv w [tap][cpair][o] half2
__device__ float g_part[2 * BATCH * CC * NPIX];   // k7 split-K partials
__device__ float g_bnA[4 * CC];
__device__ float g_bnB[4 * CC];
__device__ float g_S[BATCH * CC];
__device__ float g_attnw[4 * BATCH * CC];
__device__ float g_qkvwT[768 * 256];
__device__ float g_outwT[256 * 256];

// half2-unit branch offsets: k1@0(1 tap), k3@32768(9), k5@327680(25), k7@1146880(49)
#define WH_OFF1 0
#define WH_OFF3 32768
#define WH_OFF5 327680
#define WH_OFF7 1146880

__device__ __forceinline__ float to_tf32(float x) {
    uint32_t y; asm("cvt.rna.tf32.f32 %0, %1;" : "=r"(y) : "f"(x));
    return __uint_as_float(y);
}
__device__ __forceinline__ uint32_t to_tf32_u(float x) {
    uint32_t y; asm("cvt.rna.tf32.f32 %0, %1;" : "=r"(y) : "f"(x));
    return y;
}
__device__ __forceinline__ void mma_tf32(float* d, const uint32_t* a, const uint32_t* b) {
    asm volatile(
        "mma.sync.aligned.m16n8k8.row.col.f32.tf32.tf32.f32 "
        "{%0,%1,%2,%3}, {%4,%5,%6,%7}, {%8,%9}, {%0,%1,%2,%3};"
        : "+f"(d[0]), "+f"(d[1]), "+f"(d[2]), "+f"(d[3])
        : "r"(a[0]), "r"(a[1]), "r"(a[2]), "r"(a[3]), "r"(b[0]), "r"(b[1]));
}
// fp16 K=16 mma: 2x MACs per instruction vs tf32 K=8
__device__ __forceinline__ void mma_f16(float* d, const uint32_t* a, const uint32_t* b) {
    asm volatile(
        "mma.sync.aligned.m16n8k16.row.col.f32.f16.f16.f32 "
        "{%0,%1,%2,%3}, {%4,%5,%6,%7}, {%8,%9}, {%0,%1,%2,%3};"
        : "+f"(d[0]), "+f"(d[1]), "+f"(d[2]), "+f"(d[3])
        : "r"(a[0]), "r"(a[1]), "r"(a[2]), "r"(a[3]), "r"(b[0]), "r"(b[1]));
}

// ---------------------------------------------------------------------------
// Conv weights OIHW -> [tap][cpair][o] half2; cpair cp=chunk*8+pi holds
// channels (chunk*16+2pi, +1)
// ---------------------------------------------------------------------------
__global__ void wtrans_kernel(const float* __restrict__ w1, const float* __restrict__ w3,
                              const float* __restrict__ w5, const float* __restrict__ w7) {
    int idx = blockIdx.x * 256 + threadIdx.x;
    if (idx >= 2752512) return;
    const float* src; int k2, base;
    if (idx < 327680)       { if (idx < 32768) { src = w1; k2 = 1;  base = 0; }
                              else              { src = w3; k2 = 9;  base = 32768; } }
    else if (idx < 1146880) { src = w5; k2 = 25; base = 327680; }
    else                    { src = w7; k2 = 49; base = 1146880; }
    int r   = idx - base;
    int o   = r & 255;
    int cp  = (r >> 8) & 127;
    int tap = r >> 15;
    int cx  = (cp >> 3) * 16 + (cp & 7) * 2;
    g_wH2[idx] = __floats2half2_rn(src[(o * 256 + cx) * k2 + tap],
                                   src[(o * 256 + cx + 1) * k2 + tap]);
}

__global__ void wsplit_kernel(const float* __restrict__ qkv_w, const float* __restrict__ out_w) {
    int idx = blockIdx.x * 256 + threadIdx.x;
    if (idx < 196608) {
        int m = idx / 256, k = idx & 255;
        g_qkvwT[k * 768 + m] = to_tf32(qkv_w[idx]);
    } else {
        int r = idx - 196608;
        int m = r / 256, k = r & 255;
        g_outwT[k * 256 + m] = to_tf32(out_w[r]);
    }
}

// ---------------------------------------------------------------------------
// GEMM via tf32 mma (unchanged from R10 - passing)
// ---------------------------------------------------------------------------
#define GW_STRIDE 72
#define GX_STRIDE 264
__global__ __launch_bounds__(256, 3) void gemm_mma_kernel(
    const float* __restrict__ WT, const float* __restrict__ X, float* __restrict__ D, int M) {
    __shared__ float sW[16 * GW_STRIDE];
    __shared__ float sX[16 * GX_STRIDE];
    int tid = threadIdx.x;
    int n0 = blockIdx.x * 256, m0 = blockIdx.y * 64, b = blockIdx.z;
    const float* Xb = X + (size_t)b * 256 * NPIX;
    float* Db = D + (size_t)b * M * NPIX;
    int wid = tid >> 5, lane = tid & 31;
    int g = lane >> 2, tq = lane & 3;
    int mw = (wid >> 2) * 32, nw = (wid & 3) * 64;
    float acc[2][8][4] = {};
    for (int k0 = 0; k0 < 256; k0 += 16) {
        __syncthreads();
        { int k = tid >> 4, col = (tid & 15) * 4;
          *(float4*)&sW[k * GW_STRIDE + col] = *(const float4*)&WT[(size_t)(k0 + k) * M + m0 + col]; }
        for (int i = tid; i < 1024; i += 256) {
            int k = i >> 6, c4 = (i & 63) * 4;
            float4 v = *(const float4*)&Xb[(size_t)(k0 + k) * NPIX + n0 + c4];
            v.x = to_tf32(v.x); v.y = to_tf32(v.y); v.z = to_tf32(v.z); v.w = to_tf32(v.w);
            *(float4*)&sX[k * GX_STRIDE + c4] = v;
        }
        __syncthreads();
#pragma unroll
        for (int s = 0; s < 2; s++) {
            int k = 8 * s + tq;
            uint32_t a[2][4];
#pragma unroll
            for (int t = 0; t < 2; t++) {
                int m = mw + 16 * t + g;
                a[t][0] = __float_as_uint(sW[k * GW_STRIDE + m]);
                a[t][1] = __float_as_uint(sW[k * GW_STRIDE + m + 8]);
                a[t][2] = __float_as_uint(sW[(k + 4) * GW_STRIDE + m]);
                a[t][3] = __float_as_uint(sW[(k + 4) * GW_STRIDE + m + 8]);
            }
#pragma unroll
            for (int j = 0; j < 8; j++) {
                int nj = nw + 8 * j + g;
                uint32_t bb[2] = {__float_as_uint(sX[k * GX_STRIDE + nj]),
                                  __float_as_uint(sX[(k + 4) * GX_STRIDE + nj])};
#pragma unroll
                for (int t = 0; t < 2; t++) mma_tf32(acc[t][j], a[t], bb);
            }
        }
    }
#pragma unroll
    for (int t = 0; t < 2; t++) {
        int o = m0 + mw + 16 * t + g;
#pragma unroll
        for (int j = 0; j < 8; j++) {
            int n = n0 + nw + 8 * j + 2 * tq;
            *(float2*)&Db[(size_t)o * NPIX + n] = make_float2(acc[t][j][0], acc[t][j][1]);
            *(float2*)&Db[(size_t)(o + 8) * NPIX + n] = make_float2(acc[t][j][2], acc[t][j][3]);
        }
    }
}

// ---------------------------------------------------------------------------
// Attention via tf32 mma (unchanged from R10 - passing)
// ---------------------------------------------------------------------------
#define ATTN_SMEM_BYTES 55296
__global__ __launch_bounds__(256) void attn_mma_kernel(const float* __restrict__ qkv,
                                                       float* __restrict__ ctx) {
    extern __shared__ float sm[];
    float* sK = sm; float* sV = sm + 2304; float* sQ = sm + 4608;
    int t = threadIdx.x, wid = t >> 5, lane = t & 31;
    int g = lane >> 2, tq = lane & 3, qw = wid * 16;
    float* sP = sm + 4608 + wid * (16 * 72);
    int bh = blockIdx.y, b = bh >> 3, h = bh & 7;
    int q0 = blockIdx.x * 128;
    const float* base = qkv + (size_t)b * (3 * CC * NPIX);
    const float* qp = base + (h * HDIM) * NPIX;
    const float* kp = base + (CC + h * HDIM) * NPIX;
    const float* vp = base + (2 * CC + h * HDIM) * NPIX;
    const float scale = 0.17677669529663687f;
    for (int i = t; i < 1024; i += 256) {
        int d = i >> 5, q4 = (i & 31) * 4;
        float4 v = *(const float4*)&qp[(size_t)d * NPIX + q0 + q4];
        sQ[(q4 + 0) * 36 + d] = v.x * scale; sQ[(q4 + 1) * 36 + d] = v.y * scale;
        sQ[(q4 + 2) * 36 + d] = v.z * scale; sQ[(q4 + 3) * 36 + d] = v.w * scale;
    }
    __syncthreads();
    uint32_t qf[4][4];
#pragma unroll
    for (int kc = 0; kc < 4; kc++)
#pragma unroll
        for (int r = 0; r < 4; r++) {
            int row = qw + ((r & 1) ? g + 8 : g);
            int col = 8 * kc + tq + ((r >> 1) ? 4 : 0);
            qf[kc][r] = to_tf32_u(sQ[row * 36 + col]);
        }
    float mrow[2] = {-1e30f, -1e30f}, lrow[2] = {0.f, 0.f}, oacc[4][4] = {};
    for (int k0 = 0; k0 < NPIX; k0 += 64) {
        __syncthreads();
        for (int i = t; i < 512; i += 256) {
            int d = i >> 4, c4 = (i & 15) * 4;
            float4 v = *(const float4*)&kp[(size_t)d * NPIX + k0 + c4];
            v.x = to_tf32(v.x); v.y = to_tf32(v.y); v.z = to_tf32(v.z); v.w = to_tf32(v.w);
            *(float4*)&sK[d * 72 + c4] = v;
            float4 vv = *(const float4*)&vp[(size_t)d * NPIX + k0 + c4];
            vv.x = to_tf32(vv.x); vv.y = to_tf32(vv.y); vv.z = to_tf32(vv.z); vv.w = to_tf32(vv.w);
            *(float4*)&sV[d * 72 + c4] = vv;
        }
        __syncthreads();
        float sv[8][4];
#pragma unroll
        for (int nt = 0; nt < 8; nt++) {
            float acc[4] = {0.f, 0.f, 0.f, 0.f};
#pragma unroll
            for (int kc = 0; kc < 4; kc++) {
                int i0 = (8 * kc + tq) * 72 + 8 * nt + g;
                int i1 = (8 * kc + tq + 4) * 72 + 8 * nt + g;
                uint32_t bb[2] = {__float_as_uint(sK[i0]), __float_as_uint(sK[i1])};
                mma_tf32(acc, qf[kc], bb);
            }
            sv[nt][0] = acc[0]; sv[nt][1] = acc[1]; sv[nt][2] = acc[2]; sv[nt][3] = acc[3];
        }
        float tm0 = -1e30f, tm1 = -1e30f;
#pragma unroll
        for (int nt = 0; nt < 8; nt++) {
            tm0 = fmaxf(tm0, fmaxf(sv[nt][0], sv[nt][1]));
            tm1 = fmaxf(tm1, fmaxf(sv[nt][2], sv[nt][3]));
        }
        tm0 = fmaxf(tm0, __shfl_xor_sync(0xffffffffu, tm0, 1));
        tm0 = fmaxf(tm0, __shfl_xor_sync(0xffffffffu, tm0, 2));
        tm1 = fmaxf(tm1, __shfl_xor_sync(0xffffffffu, tm1, 1));
        tm1 = fmaxf(tm1, __shfl_xor_sync(0xffffffffu, tm1, 2));
        float m0n = fmaxf(mrow[0], tm0), m1n = fmaxf(mrow[1], tm1);
        float c0 = __expf(mrow[0] - m0n), c1 = __expf(mrow[1] - m1n);
        mrow[0] = m0n; mrow[1] = m1n;
        lrow[0] *= c0; lrow[1] *= c1;
#pragma unroll
        for (int dt = 0; dt < 4; dt++) {
            oacc[dt][0] *= c0; oacc[dt][1] *= c0; oacc[dt][2] *= c1; oacc[dt][3] *= c1;
        }
#pragma unroll
        for (int nt = 0; nt < 8; nt++) {
            float p0 = __expf(sv[nt][0] - m0n), p1 = __expf(sv[nt][1] - m0n);
            float p2 = __expf(sv[nt][2] - m1n), p3 = __expf(sv[nt][3] - m1n);
            lrow[0] += p0 + p1; lrow[1] += p2 + p3;
            *(float2*)&sP[g * 72 + 8 * nt + 2 * tq] = make_float2(to_tf32(p0), to_tf32(p1));
            *(float2*)&sP[(g + 8) * 72 + 8 * nt + 2 * tq] = make_float2(to_tf32(p2), to_tf32(p3));
        }
        __syncwarp();
#pragma unroll
        for (int kc = 0; kc < 8; kc++) {
            uint32_t a[4];
            a[0] = __float_as_uint(sP[g * 72 + 8 * kc + tq]);
            a[1] = __float_as_uint(sP[(g + 8) * 72 + 8 * kc + tq]);
            a[2] = __float_as_uint(sP[g * 72 + 8 * kc + tq + 4]);
            a[3] = __float_as_uint(sP[(g + 8) * 72 + 8 * kc + tq + 4]);
#pragma unroll
            for (int dt = 0; dt < 4; dt++) {
                uint32_t bb[2] = {__float_as_uint(sV[(8 * dt + g) * 72 + 8 * kc + tq]),
                                  __float_as_uint(sV[(8 * dt + g) * 72 + 8 * kc + tq + 4])};
                mma_tf32(oacc[dt], a, bb);
            }
        }
        __syncwarp();
    }
    lrow[0] += __shfl_xor_sync(0xffffffffu, lrow[0], 1);
    lrow[0] += __shfl_xor_sync(0xffffffffu, lrow[0], 2);
    lrow[1] += __shfl_xor_sync(0xffffffffu, lrow[1], 1);
    lrow[1] += __shfl_xor_sync(0xffffffffu, lrow[1], 2);
    float inv0 = 1.f / lrow[0], inv1 = 1.f / lrow[1];
    float* cp = ctx + (size_t)b * (CC * NPIX) + (size_t)(h * HDIM) * NPIX;
    int qr0 = q0 + qw + g, qr1 = qr0 + 8;
#pragma unroll
    for (int dt = 0; dt < 4; dt++) {
        int d0 = 8 * dt + 2 * tq;
        cp[(size_t)d0 * NPIX + qr0] = oacc[dt][0] * inv0;
        cp[(size_t)(d0 + 1) * NPIX + qr0] = oacc[dt][1] * inv0;
        cp[(size_t)d0 * NPIX + qr1] = oacc[dt][2] * inv1;
        cp[(size_t)(d0 + 1) * NPIX + qr1] = oacc[dt][3] * inv1;
    }
}

// ---------------------------------------------------------------------------
// Conv via fp16 m16n8k16 mma (2x MACs/instr vs tf32 k8, same 10-bit mantissa).
// Patch: 8 half2 pair-planes [14 rows x 40 cols], plane stride 584 (==8 mod 32,
//   conflict-free), zero-padded halo. A: [pi][64 o] half2, stride 72.
// CTA: M=64 out-ch x N=256 pixels, 8 warps (2m x 4n), warp tile 32x64.
// k1/k3/k5 fused BN+ReLU; k7 2 splits -> g_part + epi. 2 CTAs/SM.
// ---------------------------------------------------------------------------
#define PLH 584                        // patch plane stride (half2)
#define AHS 72                         // A plane stride (half2)
#define AH_TAP (8 * AHS)               // 576 half2 per tap
#define AH_GRP (4 * AH_TAP)
#define CONV_SMEM_BYTES ((8 * PLH + 2 * AH_GRP) * 4)   // 18688+18432 = 37120

__global__ __launch_bounds__(256, 2) void conv_mma_kernel(const float* __restrict__ in,
                                                          float* __restrict__ feats) {
    extern __shared__ half2 ch2[];
    half2* sPatch = ch2;
    half2* sA     = ch2 + 8 * PLH;

    int z = blockIdx.z;
    int ks, tap0, tap1, slot, kb, b; size_t whoff; bool fused;
    if (z < 16) { int s = z >> 3; b = z & 7; ks = 7; tap0 = s ? 24 : 0; tap1 = s ? 49 : 24;
                  slot = s; kb = 3; fused = false; whoff = WH_OFF7; }
    else if (z < 24) { b = z - 16; ks = 5; tap0 = 0; tap1 = 25; slot = 0; kb = 2; fused = true; whoff = WH_OFF5; }
    else if (z < 32) { b = z - 24; ks = 3; tap0 = 0; tap1 = 9;  slot = 0; kb = 1; fused = true; whoff = WH_OFF3; }
    else             { b = z - 32; ks = 1; tap0 = 0; tap1 = 1;  slot = 0; kb = 0; fused = true; whoff = WH_OFF1; }
    const int P = ks >> 1;
    const int rows = 8 + 2 * P;

    int n0 = blockIdx.x * 256;
    int m0 = blockIdx.y * 64;
    int r0 = n0 >> 5;
    int tid = threadIdx.x;
    int wid = tid >> 5, lane = tid & 31;
    int mw = (wid >> 2) * 32;
    int nw = (wid & 3) * 64;
    int lg = lane >> 2;
    int lk = lane & 3;

    // zero patch once (halo cols + OOB rows stay zero)
    for (int i = tid; i < (8 * PLH) / 4; i += 256)
        *(float4*)&sPatch[i * 4] = make_float4(0.f, 0.f, 0.f, 0.f);

    int njoff[8];
#pragma unroll
    for (int j = 0; j < 8; j++) {
        int n = nw + 8 * j + lg;
        njoff[j] = (n >> 5) * 40 + (n & 31) + 4;
    }

    const float* inb = in + (size_t)b * (CC * NPIX);
    float acc[2][8][4] = {};

    for (int c0 = 0; c0 < 256; c0 += 16) {
        __syncthreads();
        // patch: pair-plane pi <- channels (c0+2pi, c0+2pi+1), fp16-packed
        {
            int per_plane = rows * 8;          // float4 x-groups per plane
            int total = 8 * per_plane;
            for (int i = tid; i < total; i += 256) {
                int pi = i / per_plane;
                int rm = i - pi * per_plane;
                int py = rm >> 3;
                int xq = (rm & 7) * 4;
                int iy = r0 - P + py;
                if ((unsigned)iy < 32u) {
                    const float* s0 = &inb[(size_t)(c0 + 2 * pi) * NPIX + iy * 32 + xq];
                    const float* s1 = s0 + NPIX;
                    float4 v0 = *(const float4*)s0;
                    float4 v1 = *(const float4*)s1;
                    half2 q[4];
                    q[0] = __floats2half2_rn(v0.x, v1.x);
                    q[1] = __floats2half2_rn(v0.y, v1.y);
                    q[2] = __floats2half2_rn(v0.z, v1.z);
                    q[3] = __floats2half2_rn(v0.w, v1.w);
                    *(float4*)&sPatch[pi * PLH + py * 40 + 4 + xq] = *(float4*)q;
                }
            }
        }
        // preload first tap group: per tap 8 planes x 64 o = 128 float4
        {
            size_t cb = whoff + (size_t)(c0 >> 1) * 256;   // chunk*8*256
            int gcnt = tap1 - tap0; if (gcnt > 4) gcnt = 4;
            for (int i = tid; i < gcnt * 128; i += 256) {
                int tg = i >> 7;
                int pi = (i >> 4) & 7;
                int c4 = (i & 15) * 4;
                *(float4*)&sA[tg * AH_TAP + pi * AHS + c4] =
                    *(const float4*)&g_wH2[cb + (size_t)(tap0 + tg) * 32768 + pi * 256 + m0 + c4];
            }
        }
        __syncthreads();

        int buf = 0;
        for (int g0 = tap0; g0 < tap1; g0 += 4) {
            int gcnt = tap1 - g0; if (gcnt > 4) gcnt = 4;
            int h0 = g0 + 4;
            if (h0 < tap1) {
                int hcnt = tap1 - h0; if (hcnt > 4) hcnt = 4;
                half2* dst = sA + (buf ^ 1) * AH_GRP;
                size_t cb = whoff + (size_t)(c0 >> 1) * 256;
                for (int i = tid; i < hcnt * 128; i += 256) {
                    int tg = i >> 7;
                    int pi = (i >> 4) & 7;
                    int c4 = (i & 15) * 4;
                    *(float4*)&dst[tg * AH_TAP + pi * AHS + c4] =
                        *(const float4*)&g_wH2[cb + (size_t)(h0 + tg) * 32768 + pi * 256 + m0 + c4];
                }
            }
            for (int ti = 0; ti < gcnt; ti++) {
                int tap = g0 + ti;
                int ty = tap / ks;
                int tx = tap - ty * ks;
                int tadd = ty * 40 + tx - P;
                const uint32_t* At = (const uint32_t*)(sA + buf * AH_GRP + ti * AH_TAP);
                const uint32_t* Pp = (const uint32_t*)sPatch;
                // A fragments: planes lk / lk+4, rows {m, m+8}
                uint32_t a[2][4];
#pragma unroll
                for (int t = 0; t < 2; t++) {
                    int m = mw + 16 * t + lg;
                    a[t][0] = At[lk * AHS + m];
                    a[t][1] = At[lk * AHS + m + 8];
                    a[t][2] = At[(lk + 4) * AHS + m];
                    a[t][3] = At[(lk + 4) * AHS + m + 8];
                }
                uint32_t bb[8][2];
#pragma unroll
                for (int j = 0; j < 8; j++) {
                    int off = njoff[j] + tadd;
                    bb[j][0] = Pp[lk * PLH + off];
                    bb[j][1] = Pp[(lk + 4) * PLH + off];
                }
#pragma unroll
                for (int t = 0; t < 2; t++)
#pragma unroll
                    for (int j = 0; j < 8; j++) mma_f16(acc[t][j], a[t], bb[j]);
            }
            __syncthreads();
            buf ^= 1;
        }
    }

    if (fused) {
        float* fp = feats + (size_t)kb * (BATCH * CC * NPIX) + (size_t)b * (CC * NPIX);
#pragma unroll
        for (int t = 0; t < 2; t++) {
            int o = m0 + mw + 16 * t + lg;
            float A0 = g_bnA[kb * 256 + o],     B0 = g_bnB[kb * 256 + o];
            float A1 = g_bnA[kb * 256 + o + 8], B1 = g_bnB[kb * 256 + o + 8];
#pragma unroll
            for (int j = 0; j < 8; j++) {
                int n = n0 + nw + 8 * j + 2 * lk;
                *(float2*)&fp[(size_t)o * NPIX + n] = make_float2(
                    fmaxf(acc[t][j][0] * A0 + B0, 0.f), fmaxf(acc[t][j][1] * A0 + B0, 0.f));
                *(float2*)&fp[(size_t)(o + 8) * NPIX + n] = make_float2(
                    fmaxf(acc[t][j][2] * A1 + B1, 0.f), fmaxf(acc[t][j][3] * A1 + B1, 0.f));
            }
        }
    } else {
        float* pp = g_part + (size_t)slot * (BATCH * CC * NPIX) + (size_t)b * (CC * NPIX);
#pragma unroll
        for (int t = 0; t < 2; t++) {
            int o = m0 + mw + 16 * t + lg;
#pragma unroll
            for (int j = 0; j < 8; j++) {
                int n = n0 + nw + 8 * j + 2 * lk;
                *(float2*)&pp[(size_t)o * NPIX + n] = make_float2(acc[t][j][0], acc[t][j][1]);
                *(float2*)&pp[(size_t)(o + 8) * NPIX + n] = make_float2(acc[t][j][2], acc[t][j][3]);
            }
        }
    }
}

// ---- tail (unchanged from R10) ----
__global__ void bnprep_kernel(const float* __restrict__ conv_b, const float* __restrict__ gamma,
                              const float* __restrict__ beta, const float* __restrict__ mean,
                              const float* __restrict__ var) {
    int i = threadIdx.x;
    float inv = gamma[i] * rsqrtf(var[i] + 1e-5f);
    g_bnA[i] = inv;
    g_bnB[i] = beta[i] - mean[i] * inv + conv_b[i] * inv;
}

__global__ __launch_bounds__(256) void epi_kernel(float* __restrict__ feats) {
    int row = blockIdx.x;
    int o = row & 255;
    float Aa = g_bnA[768 + o], Bb = g_bnB[768 + o];
    size_t base = (size_t)row * NPIX + threadIdx.x * 4;
    const size_t SL = (size_t)BATCH * CC * NPIX;
    float4 s0 = *(const float4*)&g_part[base];
    float4 s1 = *(const float4*)&g_part[SL + base];
    float4 v;
    v.x = fmaxf((s0.x + s1.x) * Aa + Bb, 0.f);
    v.y = fmaxf((s0.y + s1.y) * Aa + Bb, 0.f);
    v.z = fmaxf((s0.z + s1.z) * Aa + Bb, 0.f);
    v.w = fmaxf((s0.w + s1.w) * Aa + Bb, 0.f);
    *(float4*)&feats[3 * SL + base] = v;
}

__global__ __launch_bounds__(128) void sreduce_kernel(float* __restrict__ S) {
    int bc = blockIdx.x, t = threadIdx.x;
    float s = 0.f;
#pragma unroll
    for (int k = 0; k < 4; k++) {
        const float* p = g_feats + ((size_t)k * (BATCH * CC) + bc) * NPIX;
        for (int n = t; n < NPIX; n += 128) s += p[n];
    }
#pragma unroll
    for (int off = 16; off; off >>= 1) s += __shfl_down_sync(0xffffffffu, s, off);
    __shared__ float red[4];
    if ((t & 31) == 0) red[t >> 5] = s;
    __syncthreads();
    if (t == 0) S[bc] = (red[0] + red[1] + red[2] + red[3]) * (1.f / 1024.f);
}

__global__ __launch_bounds__(256) void select_kernel(
    const float* __restrict__ S, const float* __restrict__ fc_w,
    const float* __restrict__ fc_b, const float* __restrict__ fcs_w,
    const float* __restrict__ fcs_b, float* __restrict__ attnw) {
    __shared__ float Ss[BATCH * CC];
    __shared__ float Zs[BATCH * DDIM];
    int t = threadIdx.x;
    for (int i = t; i < BATCH * CC; i += 256) Ss[i] = S[i];
    __syncthreads();
    { int b = t >> 5, d = t & 31;
      float z = fc_b[d];
      const float* wr = fc_w + d * CC;
      for (int c = 0; c < CC; c++) z += Ss[b * CC + c] * wr[c];
      Zs[b * DDIM + d] = z; }
    __syncthreads();
    for (int it = 0; it < 8; it++) {
        int idx = it * 256 + t;
        int b = idx >> 8, c = idx & 255;
        float lg[4];
#pragma unroll
        for (int k = 0; k < 4; k++) {
            float v = fcs_b[k * CC + c];
            const float* wp = fcs_w + ((size_t)k * CC + c) * DDIM;
#pragma unroll
            for (int d = 0; d < DDIM; d++) v += wp[d] * Zs[b * DDIM + d];
            lg[k] = v;
        }
        float mx = fmaxf(fmaxf(lg[0], lg[1]), fmaxf(lg[2], lg[3]));
        float e0 = __expf(lg[0] - mx), e1 = __expf(lg[1] - mx);
        float e2 = __expf(lg[2] - mx), e3 = __expf(lg[3] - mx);
        float inv = 1.f / (e0 + e1 + e2 + e3);
        attnw[idx] = e0 * inv;
        attnw[2048 + idx] = e1 * inv;
        attnw[4096 + idx] = e2 * inv;
        attnw[6144 + idx] = e3 * inv;
    }
}

__global__ __launch_bounds__(256) void combine_kernel(const float* __restrict__ attnw,
                                                      float* __restrict__ out) {
    int idx = blockIdx.x * 256 + threadIdx.x;
    if (idx >= BATCH * CC * NPIX) return;
    int bc = idx >> 10;
    const size_t KS = (size_t)BATCH * CC * NPIX;
    out[idx] = attnw[bc] * g_feats[idx] +
               attnw[2048 + bc] * g_feats[KS + idx] +
               attnw[4096 + bc] * g_feats[2 * KS + idx] +
               attnw[6144 + bc] * g_feats[3 * KS + idx];
}

extern "C" void kernel_launch(void* const* d_in, const int* in_sizes, int n_in,
                              void* d_out, int out_size) {
    const float* x      = (const float*)d_in[0];
    const float* qkv_w  = (const float*)d_in[1];
    const float* out_w  = (const float*)d_in[2];
    const float* w1     = (const float*)d_in[3];
    const float* w3     = (const float*)d_in[4];
    const float* w5     = (const float*)d_in[5];
    const float* w7     = (const float*)d_in[6];
    const float* conv_b = (const float*)d_in[7];
    const float* gamma  = (const float*)d_in[8];
    const float* beta   = (const float*)d_in[9];
    const float* mean   = (const float*)d_in[10];
    const float* var    = (const float*)d_in[11];
    const float* fc_w   = (const float*)d_in[12];
    const float* fc_b   = (const float*)d_in[13];
    const float* fcs_w  = (const float*)d_in[14];
    const float* fcs_b  = (const float*)d_in[15];
    float* out = (float*)d_out;

    float *p_qkv, *p_ctx, *p_ao, *p_feats, *p_S, *p_attnw, *p_qw, *p_ow;
    cudaGetSymbolAddress((void**)&p_qkv,   g_qkv);
    cudaGetSymbolAddress((void**)&p_ctx,   g_ctx);
    cudaGetSymbolAddress((void**)&p_ao,    g_ao);
    cudaGetSymbolAddress((void**)&p_feats, g_feats);
    cudaGetSymbolAddress((void**)&p_S,     g_S);
    cudaGetSymbolAddress((void**)&p_attnw, g_attnw);
    cudaGetSymbolAddress((void**)&p_qw,    g_qkvwT);
    cudaGetSymbolAddress((void**)&p_ow,    g_outwT);

    static int attr_set = 0;
    if (!attr_set) {
        cudaFuncSetAttribute(attn_mma_kernel, cudaFuncAttributeMaxDynamicSharedMemorySize,
                             ATTN_SMEM_BYTES);
        cudaFuncSetAttribute(conv_mma_kernel, cudaFuncAttributeMaxDynamicSharedMemorySize,
                             CONV_SMEM_BYTES);
        attr_set = 1;
    }

    wtrans_kernel<<<10752, 256>>>(w1, w3, w5, w7);
    wsplit_kernel<<<1024, 256>>>(qkv_w, out_w);
    bnprep_kernel<<<1, 1024>>>(conv_b, gamma, beta, mean, var);

    gemm_mma_kernel<<<dim3(4, 12, 8), 256>>>(p_qw, x, p_qkv, 768);
    attn_mma_kernel<<<dim3(8, 64), 256, ATTN_SMEM_BYTES>>>(p_qkv, p_ctx);
    gemm_mma_kernel<<<dim3(4, 4, 8), 256>>>(p_ow, p_ctx, p_ao, 256);

    conv_mma_kernel<<<dim3(4, 4, 40), 256, CONV_SMEM_BYTES>>>(p_ao, p_feats);
    epi_kernel<<<2048, 256>>>(p_feats);

    sreduce_kernel<<<2048, 128>>>(p_S);
    select_kernel<<<1, 256>>>(p_S, fc_w, fc_b, fcs_w, fcs_b, p_attnw);
    combine_kernel<<<8192, 256>>>(p_attnw, out);
}

// round 16
// speedup vs baseline: 1.4952x; 1.0990x over previous
#include <cuda_runtime.h>
#include <cuda_fp16.h>
#include <cstdint>

#define BATCH 8
#define CC 256
#define NPIX 1024
#define HDIM 32
#define DDIM 32

__device__ float g_qkv[BATCH * 3 * CC * NPIX];
__device__ float g_ctx[BATCH * CC * NPIX];
__device__ float g_ao[BATCH * CC * NPIX];
__device__ float g_feats[4 * BATCH * CC * NPIX];
__device__ half2 g_wH2[2752512];                  // conv w [tap][cpair][o] half2
__device__ float g_part[2 * BATCH * CC * NPIX];
__device__ float g_bnA[4 * CC];
__device__ float g_bnB[4 * CC];
__device__ float g_S[BATCH * CC];
__device__ float g_attnw[4 * BATCH * CC];
__device__ half2 g_qkvwH[128 * 768];              // [kpair][m] half2
__device__ half2 g_outwH[128 * 256];

#define WH_OFF1 0
#define WH_OFF3 32768
#define WH_OFF5 327680
#define WH_OFF7 1146880

// fp16 K=16 mma
__device__ __forceinline__ void mma_f16(float* d, const uint32_t* a, const uint32_t* b) {
    asm volatile(
        "mma.sync.aligned.m16n8k16.row.col.f32.f16.f16.f32 "
        "{%0,%1,%2,%3}, {%4,%5,%6,%7}, {%8,%9}, {%0,%1,%2,%3};"
        : "+f"(d[0]), "+f"(d[1]), "+f"(d[2]), "+f"(d[3])
        : "r"(a[0]), "r"(a[1]), "r"(a[2]), "r"(a[3]), "r"(b[0]), "r"(b[1]));
}
__device__ __forceinline__ uint32_t h2u(half2 h) { return *(uint32_t*)&h; }

// ---------------------------------------------------------------------------
// Conv weights OIHW -> [tap][cpair][o] half2 (validated R14)
// ---------------------------------------------------------------------------
__global__ void wtrans_kernel(const float* __restrict__ w1, const float* __restrict__ w3,
                              const float* __restrict__ w5, const float* __restrict__ w7) {
    int idx = blockIdx.x * 256 + threadIdx.x;
    if (idx >= 2752512) return;
    const float* src; int k2, base;
    if (idx < 327680)       { if (idx < 32768) { src = w1; k2 = 1;  base = 0; }
                              else              { src = w3; k2 = 9;  base = 32768; } }
    else if (idx < 1146880) { src = w5; k2 = 25; base = 327680; }
    else                    { src = w7; k2 = 49; base = 1146880; }
    int r   = idx - base;
    int o   = r & 255;
    int cp  = (r >> 8) & 127;
    int tap = r >> 15;
    int cx  = (cp >> 3) * 16 + (cp & 7) * 2;
    g_wH2[idx] = __floats2half2_rn(src[(o * 256 + cx) * k2 + tap],
                                   src[(o * 256 + cx + 1) * k2 + tap]);
}

// Projection weights -> half2 [kpair][m]
__global__ void wsplit_kernel(const float* __restrict__ qkv_w, const float* __restrict__ out_w) {
    int idx = blockIdx.x * 256 + threadIdx.x;  // 131072 total
    if (idx < 98304) {
        int kp = idx / 768, m = idx - kp * 768;
        g_qkvwH[idx] = __floats2half2_rn(qkv_w[m * 256 + 2 * kp], qkv_w[m * 256 + 2 * kp + 1]);
    } else {
        int r = idx - 98304;
        int kp = r >> 8, m = r & 255;
        g_outwH[r] = __floats2half2_rn(out_w[m * 256 + 2 * kp], out_w[m * 256 + 2 * kp + 1]);
    }
}

// ---------------------------------------------------------------------------
// GEMM via fp16 m16n8k16. CTA M=64 x N=256, 8 warps (2m x 4n), 3 CTAs/SM.
// ---------------------------------------------------------------------------
#define GWH 72
#define GXH 264
__global__ __launch_bounds__(256, 3) void gemm_mma_kernel(
    const half2* __restrict__ WH, const float* __restrict__ X, float* __restrict__ D, int M) {
    __shared__ half2 sW[8 * GWH];
    __shared__ half2 sX[8 * GXH];
    int tid = threadIdx.x;
    int n0 = blockIdx.x * 256, m0 = blockIdx.y * 64, b = blockIdx.z;
    const float* Xb = X + (size_t)b * 256 * NPIX;
    float* Db = D + (size_t)b * M * NPIX;
    int wid = tid >> 5, lane = tid & 31;
    int g = lane >> 2, tq = lane & 3;
    int mw = (wid >> 2) * 32, nw = (wid & 3) * 64;
    float acc[2][8][4] = {};
    for (int k0 = 0; k0 < 256; k0 += 16) {
        __syncthreads();
        if (tid < 128) {   // W: 8 kp x 64 m = 128 float4
            int kp = tid >> 4, c4 = (tid & 15) * 4;
            *(float4*)&sW[kp * GWH + c4] =
                *(const float4*)&WH[(size_t)(k0 / 2 + kp) * M + m0 + c4];
        }
        for (int i = tid; i < 512; i += 256) {  // X: pack rows 2kp,2kp+1
            int kp = i >> 6, n4 = (i & 63) * 4;
            const float* s0 = &Xb[(size_t)(k0 + 2 * kp) * NPIX + n0 + n4];
            float4 v0 = *(const float4*)s0;
            float4 v1 = *(const float4*)(s0 + NPIX);
            half2 q[4];
            q[0] = __floats2half2_rn(v0.x, v1.x);
            q[1] = __floats2half2_rn(v0.y, v1.y);
            q[2] = __floats2half2_rn(v0.z, v1.z);
            q[3] = __floats2half2_rn(v0.w, v1.w);
            *(float4*)&sX[kp * GXH + n4] = *(float4*)q;
        }
        __syncthreads();
        uint32_t a[2][4];
#pragma unroll
        for (int t = 0; t < 2; t++) {
            int m = mw + 16 * t + g;
            a[t][0] = h2u(sW[tq * GWH + m]);
            a[t][1] = h2u(sW[tq * GWH + m + 8]);
            a[t][2] = h2u(sW[(tq + 4) * GWH + m]);
            a[t][3] = h2u(sW[(tq + 4) * GWH + m + 8]);
        }
#pragma unroll
        for (int j = 0; j < 8; j++) {
            int nj = nw + 8 * j + g;
            uint32_t bb[2] = {h2u(sX[tq * GXH + nj]), h2u(sX[(tq + 4) * GXH + nj])};
#pragma unroll
            for (int t = 0; t < 2; t++) mma_f16(acc[t][j], a[t], bb);
        }
    }
#pragma unroll
    for (int t = 0; t < 2; t++) {
        int o = m0 + mw + 16 * t + g;
#pragma unroll
        for (int j = 0; j < 8; j++) {
            int n = n0 + nw + 8 * j + 2 * tq;
            *(float2*)&Db[(size_t)o * NPIX + n] = make_float2(acc[t][j][0], acc[t][j][1]);
            *(float2*)&Db[(size_t)(o + 8) * NPIX + n] = make_float2(acc[t][j][2], acc[t][j][3]);
        }
    }
}

// ---------------------------------------------------------------------------
// Attention via fp16 m16n8k16. CTA 128q x (b,h), 8 warps x 16q, 64-key tiles.
// smem layout (half2): sK[16*72]@0, sV[32*40]@1152, sQ[128*20]@2432 (overlaid
// by sP[8 warps * 16*36]@2432 .. 7040). Total 7040 half2 = 28160 B.
// ---------------------------------------------------------------------------
__global__ __launch_bounds__(256) void attn_mma_kernel(const float* __restrict__ qkv,
                                                       float* __restrict__ ctx) {
    __shared__ half2 sm2[7040];
    half2* sK = sm2;                 // 16*72 = 1152
    half2* sV = sm2 + 1152;          // 32*40 = 1280
    half2* sQ = sm2 + 2432;          // 128*20 = 2560 (overlaid by sP)
    int t = threadIdx.x, wid = t >> 5, lane = t & 31;
    int g = lane >> 2, tq = lane & 3, qw = wid * 16;
    half2* sP = sm2 + 2432 + wid * 576;   // 16*36 per warp; ends at 7040

    int bh = blockIdx.y, b = bh >> 3, h = bh & 7;
    int q0 = blockIdx.x * 128;
    const float* base = qkv + (size_t)b * (3 * CC * NPIX);
    const float* qp = base + (h * HDIM) * NPIX;
    const float* kp = base + (CC + h * HDIM) * NPIX;
    const float* vp = base + (2 * CC + h * HDIM) * NPIX;
    const float scale = 0.17677669529663687f;

    // Q -> sQ[q][d2] pair-packed over d, scaled
    for (int i = t; i < 512; i += 256) {
        int d2 = i >> 5, q4 = (i & 31) * 4;
        const float* s0 = &qp[(size_t)(2 * d2) * NPIX + q0 + q4];
        float4 v0 = *(const float4*)s0;
        float4 v1 = *(const float4*)(s0 + NPIX);
        sQ[(q4 + 0) * 20 + d2] = __floats2half2_rn(v0.x * scale, v1.x * scale);
        sQ[(q4 + 1) * 20 + d2] = __floats2half2_rn(v0.y * scale, v1.y * scale);
        sQ[(q4 + 2) * 20 + d2] = __floats2half2_rn(v0.z * scale, v1.z * scale);
        sQ[(q4 + 3) * 20 + d2] = __floats2half2_rn(v0.w * scale, v1.w * scale);
    }
    __syncthreads();

    uint32_t qf[2][4];
#pragma unroll
    for (int kc = 0; kc < 2; kc++)
#pragma unroll
        for (int r = 0; r < 4; r++) {
            int row = qw + ((r & 1) ? g + 8 : g);
            int d2 = 8 * kc + tq + ((r >> 1) ? 4 : 0);
            qf[kc][r] = h2u(sQ[row * 20 + d2]);
        }

    float mrow[2] = {-1e30f, -1e30f}, lrow[2] = {0.f, 0.f}, oacc[4][4] = {};

    for (int k0 = 0; k0 < NPIX; k0 += 64) {
        __syncthreads();
        // K: pair-pack over d -> sK[d2][key]; V: pair-pack over keys -> sV[kp][d]
        for (int i = t; i < 768; i += 256) {
            if (i < 256) {
                int d2 = i >> 4, k4 = (i & 15) * 4;
                const float* s0 = &kp[(size_t)(2 * d2) * NPIX + k0 + k4];
                float4 v0 = *(const float4*)s0;
                float4 v1 = *(const float4*)(s0 + NPIX);
                half2 q[4];
                q[0] = __floats2half2_rn(v0.x, v1.x);
                q[1] = __floats2half2_rn(v0.y, v1.y);
                q[2] = __floats2half2_rn(v0.z, v1.z);
                q[3] = __floats2half2_rn(v0.w, v1.w);
                *(float4*)&sK[d2 * 72 + k4] = *(float4*)q;
            } else {
                int r = i - 256;
                int d = r >> 4, k4 = (r & 15) * 4;
                float4 v = *(const float4*)&vp[(size_t)d * NPIX + k0 + k4];
                int kp2 = k4 >> 1;
                sV[kp2 * 40 + d]       = __floats2half2_rn(v.x, v.y);
                sV[(kp2 + 1) * 40 + d] = __floats2half2_rn(v.z, v.w);
            }
        }
        __syncthreads();

        float sv[8][4];
#pragma unroll
        for (int nt = 0; nt < 8; nt++) {
            float acc[4] = {0.f, 0.f, 0.f, 0.f};
#pragma unroll
            for (int kc = 0; kc < 2; kc++) {
                uint32_t bb[2] = {h2u(sK[(8 * kc + tq) * 72 + 8 * nt + g]),
                                  h2u(sK[(8 * kc + tq + 4) * 72 + 8 * nt + g])};
                mma_f16(acc, qf[kc], bb);
            }
            sv[nt][0] = acc[0]; sv[nt][1] = acc[1]; sv[nt][2] = acc[2]; sv[nt][3] = acc[3];
        }

        float tm0 = -1e30f, tm1 = -1e30f;
#pragma unroll
        for (int nt = 0; nt < 8; nt++) {
            tm0 = fmaxf(tm0, fmaxf(sv[nt][0], sv[nt][1]));
            tm1 = fmaxf(tm1, fmaxf(sv[nt][2], sv[nt][3]));
        }
        tm0 = fmaxf(tm0, __shfl_xor_sync(0xffffffffu, tm0, 1));
        tm0 = fmaxf(tm0, __shfl_xor_sync(0xffffffffu, tm0, 2));
        tm1 = fmaxf(tm1, __shfl_xor_sync(0xffffffffu, tm1, 1));
        tm1 = fmaxf(tm1, __shfl_xor_sync(0xffffffffu, tm1, 2));
        float m0n = fmaxf(mrow[0], tm0), m1n = fmaxf(mrow[1], tm1);
        float c0 = __expf(mrow[0] - m0n), c1 = __expf(mrow[1] - m1n);
        mrow[0] = m0n; mrow[1] = m1n;
        lrow[0] *= c0; lrow[1] *= c1;
#pragma unroll
        for (int dt = 0; dt < 4; dt++) {
            oacc[dt][0] *= c0; oacc[dt][1] *= c0; oacc[dt][2] *= c1; oacc[dt][3] *= c1;
        }
#pragma unroll
        for (int nt = 0; nt < 8; nt++) {
            float p0 = __expf(sv[nt][0] - m0n), p1 = __expf(sv[nt][1] - m0n);
            float p2 = __expf(sv[nt][2] - m1n), p3 = __expf(sv[nt][3] - m1n);
            lrow[0] += p0 + p1; lrow[1] += p2 + p3;
            sP[g * 36 + 4 * nt + tq]       = __floats2half2_rn(p0, p1);
            sP[(g + 8) * 36 + 4 * nt + tq] = __floats2half2_rn(p2, p3);
        }
        __syncwarp();

#pragma unroll
        for (int kc = 0; kc < 4; kc++) {
            uint32_t a[4];
            a[0] = h2u(sP[g * 36 + 8 * kc + tq]);
            a[1] = h2u(sP[(g + 8) * 36 + 8 * kc + tq]);
            a[2] = h2u(sP[g * 36 + 8 * kc + tq + 4]);
            a[3] = h2u(sP[(g + 8) * 36 + 8 * kc + tq + 4]);
#pragma unroll
            for (int dt = 0; dt < 4; dt++) {
                uint32_t bb[2] = {h2u(sV[(8 * kc + tq) * 40 + 8 * dt + g]),
                                  h2u(sV[(8 * kc + tq + 4) * 40 + 8 * dt + g])};
                mma_f16(oacc[dt], a, bb);
            }
        }
        __syncwarp();
    }

    lrow[0] += __shfl_xor_sync(0xffffffffu, lrow[0], 1);
    lrow[0] += __shfl_xor_sync(0xffffffffu, lrow[0], 2);
    lrow[1] += __shfl_xor_sync(0xffffffffu, lrow[1], 1);
    lrow[1] += __shfl_xor_sync(0xffffffffu, lrow[1], 2);
    float inv0 = 1.f / lrow[0], inv1 = 1.f / lrow[1];
    float* cp2 = ctx + (size_t)b * (CC * NPIX) + (size_t)(h * HDIM) * NPIX;
    int qr0 = q0 + qw + g, qr1 = qr0 + 8;
#pragma unroll
    for (int dt = 0; dt < 4; dt++) {
        int d0 = 8 * dt + 2 * tq;
        cp2[(size_t)d0 * NPIX + qr0] = oacc[dt][0] * inv0;
        cp2[(size_t)(d0 + 1) * NPIX + qr0] = oacc[dt][1] * inv0;
        cp2[(size_t)d0 * NPIX + qr1] = oacc[dt][2] * inv1;
        cp2[(size_t)(d0 + 1) * NPIX + qr1] = oacc[dt][3] * inv1;
    }
}

// ---------------------------------------------------------------------------
// Conv via fp16 m16n8k16 (unchanged from R14 - passing)
// ---------------------------------------------------------------------------
#define PLH 584
#define AHS 72
#define AH_TAP (8 * AHS)
#define AH_GRP (4 * AH_TAP)
#define CONV_SMEM_BYTES ((8 * PLH + 2 * AH_GRP) * 4)

__global__ __launch_bounds__(256, 2) void conv_mma_kernel(const float* __restrict__ in,
                                                          float* __restrict__ feats) {
    extern __shared__ half2 ch2[];
    half2* sPatch = ch2;
    half2* sA     = ch2 + 8 * PLH;

    int z = blockIdx.z;
    int ks, tap0, tap1, slot, kb, b; size_t whoff; bool fused;
    if (z < 16) { int s = z >> 3; b = z & 7; ks = 7; tap0 = s ? 24 : 0; tap1 = s ? 49 : 24;
                  slot = s; kb = 3; fused = false; whoff = WH_OFF7; }
    else if (z < 24) { b = z - 16; ks = 5; tap0 = 0; tap1 = 25; slot = 0; kb = 2; fused = true; whoff = WH_OFF5; }
    else if (z < 32) { b = z - 24; ks = 3; tap0 = 0; tap1 = 9;  slot = 0; kb = 1; fused = true; whoff = WH_OFF3; }
    else             { b = z - 32; ks = 1; tap0 = 0; tap1 = 1;  slot = 0; kb = 0; fused = true; whoff = WH_OFF1; }
    const int P = ks >> 1;
    const int rows = 8 + 2 * P;

    int n0 = blockIdx.x * 256;
    int m0 = blockIdx.y * 64;
    int r0 = n0 >> 5;
    int tid = threadIdx.x;
    int wid = tid >> 5, lane = tid & 31;
    int mw = (wid >> 2) * 32;
    int nw = (wid & 3) * 64;
    int lg = lane >> 2;
    int lk = lane & 3;

    for (int i = tid; i < (8 * PLH) / 4; i += 256)
        *(float4*)&sPatch[i * 4] = make_float4(0.f, 0.f, 0.f, 0.f);

    int njoff[8];
#pragma unroll
    for (int j = 0; j < 8; j++) {
        int n = nw + 8 * j + lg;
        njoff[j] = (n >> 5) * 40 + (n & 31) + 4;
    }

    const float* inb = in + (size_t)b * (CC * NPIX);
    float acc[2][8][4] = {};

    for (int c0 = 0; c0 < 256; c0 += 16) {
        __syncthreads();
        {
            int per_plane = rows * 8;
            int total = 8 * per_plane;
            for (int i = tid; i < total; i += 256) {
                int pi = i / per_plane;
                int rm = i - pi * per_plane;
                int py = rm >> 3;
                int xq = (rm & 7) * 4;
                int iy = r0 - P + py;
                if ((unsigned)iy < 32u) {
                    const float* s0 = &inb[(size_t)(c0 + 2 * pi) * NPIX + iy * 32 + xq];
                    const float* s1 = s0 + NPIX;
                    float4 v0 = *(const float4*)s0;
                    float4 v1 = *(const float4*)s1;
                    half2 q[4];
                    q[0] = __floats2half2_rn(v0.x, v1.x);
                    q[1] = __floats2half2_rn(v0.y, v1.y);
                    q[2] = __floats2half2_rn(v0.z, v1.z);
                    q[3] = __floats2half2_rn(v0.w, v1.w);
                    *(float4*)&sPatch[pi * PLH + py * 40 + 4 + xq] = *(float4*)q;
                }
            }
        }
        {
            size_t cb = whoff + (size_t)(c0 >> 1) * 256;
            int gcnt = tap1 - tap0; if (gcnt > 4) gcnt = 4;
            for (int i = tid; i < gcnt * 128; i += 256) {
                int tg = i >> 7;
                int pi = (i >> 4) & 7;
                int c4 = (i & 15) * 4;
                *(float4*)&sA[tg * AH_TAP + pi * AHS + c4] =
                    *(const float4*)&g_wH2[cb + (size_t)(tap0 + tg) * 32768 + pi * 256 + m0 + c4];
            }
        }
        __syncthreads();

        int buf = 0;
        for (int g0 = tap0; g0 < tap1; g0 += 4) {
            int gcnt = tap1 - g0; if (gcnt > 4) gcnt = 4;
            int h0 = g0 + 4;
            if (h0 < tap1) {
                int hcnt = tap1 - h0; if (hcnt > 4) hcnt = 4;
                half2* dst = sA + (buf ^ 1) * AH_GRP;
                size_t cb = whoff + (size_t)(c0 >> 1) * 256;
                for (int i = tid; i < hcnt * 128; i += 256) {
                    int tg = i >> 7;
                    int pi = (i >> 4) & 7;
                    int c4 = (i & 15) * 4;
                    *(float4*)&dst[tg * AH_TAP + pi * AHS + c4] =
                        *(const float4*)&g_wH2[cb + (size_t)(h0 + tg) * 32768 + pi * 256 + m0 + c4];
                }
            }
            for (int ti = 0; ti < gcnt; ti++) {
                int tap = g0 + ti;
                int ty = tap / ks;
                int tx = tap - ty * ks;
                int tadd = ty * 40 + tx - P;
                const uint32_t* At = (const uint32_t*)(sA + buf * AH_GRP + ti * AH_TAP);
                const uint32_t* Pp = (const uint32_t*)sPatch;
                uint32_t a[2][4];
#pragma unroll
                for (int t = 0; t < 2; t++) {
                    int m = mw + 16 * t + lg;
                    a[t][0] = At[lk * AHS + m];
                    a[t][1] = At[lk * AHS + m + 8];
                    a[t][2] = At[(lk + 4) * AHS + m];
                    a[t][3] = At[(lk + 4) * AHS + m + 8];
                }
                uint32_t bb[8][2];
#pragma unroll
                for (int j = 0; j < 8; j++) {
                    int off = njoff[j] + tadd;
                    bb[j][0] = Pp[lk * PLH + off];
                    bb[j][1] = Pp[(lk + 4) * PLH + off];
                }
#pragma unroll
                for (int t = 0; t < 2; t++)
#pragma unroll
                    for (int j = 0; j < 8; j++) mma_f16(acc[t][j], a[t], bb[j]);
            }
            __syncthreads();
            buf ^= 1;
        }
    }

    if (fused) {
        float* fp = feats + (size_t)kb * (BATCH * CC * NPIX) + (size_t)b * (CC * NPIX);
#pragma unroll
        for (int t = 0; t < 2; t++) {
            int o = m0 + mw + 16 * t + lg;
            float A0 = g_bnA[kb * 256 + o],     B0 = g_bnB[kb * 256 + o];
            float A1 = g_bnA[kb * 256 + o + 8], B1 = g_bnB[kb * 256 + o + 8];
#pragma unroll
            for (int j = 0; j < 8; j++) {
                int n = n0 + nw + 8 * j + 2 * lk;
                *(float2*)&fp[(size_t)o * NPIX + n] = make_float2(
                    fmaxf(acc[t][j][0] * A0 + B0, 0.f), fmaxf(acc[t][j][1] * A0 + B0, 0.f));
                *(float2*)&fp[(size_t)(o + 8) * NPIX + n] = make_float2(
                    fmaxf(acc[t][j][2] * A1 + B1, 0.f), fmaxf(acc[t][j][3] * A1 + B1, 0.f));
            }
        }
    } else {
        float* pp = g_part + (size_t)slot * (BATCH * CC * NPIX) + (size_t)b * (CC * NPIX);
#pragma unroll
        for (int t = 0; t < 2; t++) {
            int o = m0 + mw + 16 * t + lg;
#pragma unroll
            for (int j = 0; j < 8; j++) {
                int n = n0 + nw + 8 * j + 2 * lk;
                *(float2*)&pp[(size_t)o * NPIX + n] = make_float2(acc[t][j][0], acc[t][j][1]);
                *(float2*)&pp[(size_t)(o + 8) * NPIX + n] = make_float2(acc[t][j][2], acc[t][j][3]);
            }
        }
    }
}

// ---- tail (unchanged) ----
__global__ void bnprep_kernel(const float* __restrict__ conv_b, const float* __restrict__ gamma,
                              const float* __restrict__ beta, const float* __restrict__ mean,
                              const float* __restrict__ var) {
    int i = threadIdx.x;
    float inv = gamma[i] * rsqrtf(var[i] + 1e-5f);
    g_bnA[i] = inv;
    g_bnB[i] = beta[i] - mean[i] * inv + conv_b[i] * inv;
}

__global__ __launch_bounds__(256) void epi_kernel(float* __restrict__ feats) {
    int row = blockIdx.x;
    int o = row & 255;
    float Aa = g_bnA[768 + o], Bb = g_bnB[768 + o];
    size_t base = (size_t)row * NPIX + threadIdx.x * 4;
    const size_t SL = (size_t)BATCH * CC * NPIX;
    float4 s0 = *(const float4*)&g_part[base];
    float4 s1 = *(const float4*)&g_part[SL + base];
    float4 v;
    v.x = fmaxf((s0.x + s1.x) * Aa + Bb, 0.f);
    v.y = fmaxf((s0.y + s1.y) * Aa + Bb, 0.f);
    v.z = fmaxf((s0.z + s1.z) * Aa + Bb, 0.f);
    v.w = fmaxf((s0.w + s1.w) * Aa + Bb, 0.f);
    *(float4*)&feats[3 * SL + base] = v;
}

__global__ __launch_bounds__(128) void sreduce_kernel(float* __restrict__ S) {
    int bc = blockIdx.x, t = threadIdx.x;
    float s = 0.f;
#pragma unroll
    for (int k = 0; k < 4; k++) {
        const float* p = g_feats + ((size_t)k * (BATCH * CC) + bc) * NPIX;
        for (int n = t; n < NPIX; n += 128) s += p[n];
    }
#pragma unroll
    for (int off = 16; off; off >>= 1) s += __shfl_down_sync(0xffffffffu, s, off);
    __shared__ float red[4];
    if ((t & 31) == 0) red[t >> 5] = s;
    __syncthreads();
    if (t == 0) S[bc] = (red[0] + red[1] + red[2] + red[3]) * (1.f / 1024.f);
}

__global__ __launch_bounds__(256) void select_kernel(
    const float* __restrict__ S, const float* __restrict__ fc_w,
    const float* __restrict__ fc_b, const float* __restrict__ fcs_w,
    const float* __restrict__ fcs_b, float* __restrict__ attnw) {
    __shared__ float Ss[BATCH * CC];
    __shared__ float Zs[BATCH * DDIM];
    int t = threadIdx.x;
    for (int i = t; i < BATCH * CC; i += 256) Ss[i] = S[i];
    __syncthreads();
    { int b = t >> 5, d = t & 31;
      float z = fc_b[d];
      const float* wr = fc_w + d * CC;
      for (int c = 0; c < CC; c++) z += Ss[b * CC + c] * wr[c];
      Zs[b * DDIM + d] = z; }
    __syncthreads();
    for (int it = 0; it < 8; it++) {
        int idx = it * 256 + t;
        int b = idx >> 8, c = idx & 255;
        float lg[4];
#pragma unroll
        for (int k = 0; k < 4; k++) {
            float v = fcs_b[k * CC + c];
            const float* wp = fcs_w + ((size_t)k * CC + c) * DDIM;
#pragma unroll
            for (int d = 0; d < DDIM; d++) v += wp[d] * Zs[b * DDIM + d];
            lg[k] = v;
        }
        float mx = fmaxf(fmaxf(lg[0], lg[1]), fmaxf(lg[2], lg[3]));
        float e0 = __expf(lg[0] - mx), e1 = __expf(lg[1] - mx);
        float e2 = __expf(lg[2] - mx), e3 = __expf(lg[3] - mx);
        float inv = 1.f / (e0 + e1 + e2 + e3);
        attnw[idx] = e0 * inv;
        attnw[2048 + idx] = e1 * inv;
        attnw[4096 + idx] = e2 * inv;
        attnw[6144 + idx] = e3 * inv;
    }
}

__global__ __launch_bounds__(256) void combine_kernel(const float* __restrict__ attnw,
                                                      float* __restrict__ out) {
    int idx = blockIdx.x * 256 + threadIdx.x;
    if (idx >= BATCH * CC * NPIX) return;
    int bc = idx >> 10;
    const size_t KS = (size_t)BATCH * CC * NPIX;
    out[idx] = attnw[bc] * g_feats[idx] +
               attnw[2048 + bc] * g_feats[KS + idx] +
               attnw[4096 + bc] * g_feats[2 * KS + idx] +
               attnw[6144 + bc] * g_feats[3 * KS + idx];
}

extern "C" void kernel_launch(void* const* d_in, const int* in_sizes, int n_in,
                              void* d_out, int out_size) {
    const float* x      = (const float*)d_in[0];
    const float* qkv_w  = (const float*)d_in[1];
    const float* out_w  = (const float*)d_in[2];
    const float* w1     = (const float*)d_in[3];
    const float* w3     = (const float*)d_in[4];
    const float* w5     = (const float*)d_in[5];
    const float* w7     = (const float*)d_in[6];
    const float* conv_b = (const float*)d_in[7];
    const float* gamma  = (const float*)d_in[8];
    const float* beta   = (const float*)d_in[9];
    const float* mean   = (const float*)d_in[10];
    const float* var    = (const float*)d_in[11];
    const float* fc_w   = (const float*)d_in[12];
    const float* fc_b   = (const float*)d_in[13];
    const float* fcs_w  = (const float*)d_in[14];
    const float* fcs_b  = (const float*)d_in[15];
    float* out = (float*)d_out;

    float *p_qkv, *p_ctx, *p_ao, *p_feats, *p_S, *p_attnw;
    half2 *p_qw, *p_ow;
    cudaGetSymbolAddress((void**)&p_qkv,   g_qkv);
    cudaGetSymbolAddress((void**)&p_ctx,   g_ctx);
    cudaGetSymbolAddress((void**)&p_ao,    g_ao);
    cudaGetSymbolAddress((void**)&p_feats, g_feats);
    cudaGetSymbolAddress((void**)&p_S,     g_S);
    cudaGetSymbolAddress((void**)&p_attnw, g_attnw);
    cudaGetSymbolAddress((void**)&p_qw,    g_qkvwH);
    cudaGetSymbolAddress((void**)&p_ow,    g_outwH);

    static int attr_set = 0;
    if (!attr_set) {
        cudaFuncSetAttribute(conv_mma_kernel, cudaFuncAttributeMaxDynamicSharedMemorySize,
                             CONV_SMEM_BYTES);
        attr_set = 1;
    }

    wtrans_kernel<<<10752, 256>>>(w1, w3, w5, w7);
    wsplit_kernel<<<512, 256>>>(qkv_w, out_w);
    bnprep_kernel<<<1, 1024>>>(conv_b, gamma, beta, mean, var);

    gemm_mma_kernel<<<dim3(4, 12, 8), 256>>>(p_qw, x, p_qkv, 768);
    attn_mma_kernel<<<dim3(8, 64), 256>>>(p_qkv, p_ctx);
    gemm_mma_kernel<<<dim3(4, 4, 8), 256>>>(p_ow, p_ctx, p_ao, 256);

    conv_mma_kernel<<<dim3(4, 4, 40), 256, CONV_SMEM_BYTES>>>(p_ao, p_feats);
    epi_kernel<<<2048, 256>>>(p_feats);

    sreduce_kernel<<<2048, 128>>>(p_S);
    select_kernel<<<1, 256>>>(p_S, fc_w, fc_b, fcs_w, fcs_b, p_attnw);
    combine_kernel<<<8192, 256>>>(p_attnw, out);
}